// round 7
// baseline (speedup 1.0000x reference)
#include <cuda_runtime.h>
#include <cuda_bf16.h>
#include <cuda_fp16.h>
#include <math.h>
#include <cstdint>

// Problem dims (fixed for this bench)
#define BB 64
#define LL 2048
#define DD 1024
#define VV 50257
#define TOPK 5

#define NCHUNK 16
#define LPC (LL / NCHUNK)        // 128 rows per chunk

#define TNB 128                  // GEMM N tile
#define NBLK ((VV + TNB - 1) / TNB)   // 393
#define TKH 32                   // GEMM K tile (fp16 elements)
#define KPADH 40                 // padded k stride in halves (conflict-free LDS.32)
#define NCAND 64
#define BTOP 6                   // per-block-per-row top-K kept
#define CSPAD 129                // Cs row stride (floats)

// Smem blob layout (bytes):
//   [0 .. 10240)            As: 2 bufs x 64 x KPADH halves
//   [10240 .. 30720)        Bs: 2 bufs x 128 x KPADH halves
//   -- epilogue overlay on [0 .. 45312):
//   [0 .. 33024)            Cs: 64 x CSPAD floats
//   [33024 .. 45312)        tmp: 256 x BTOP u64
//   [45312 .. 45568)        s_xn: 64 floats
//   [45568 .. 46080)        s_yn: 128 floats
#define OFS_BS   10240
#define OFS_TMP  33024
#define OFS_XN   45312
#define OFS_YN   45568
#define GEMM_SMEM 46080

typedef unsigned long long u64;

// Scratch (device globals; no allocations allowed)
__device__ float4 g_part[NCHUNK][BB][DD / 4];  // mean-pool partials (4 MB)
__device__ float  g_tse[BB][DD];               // exact fp32 pooled embeddings
__device__ __half g_ts16[BB][DD];              // fp16 pooled embeddings (mma operand)
__device__ float  g_xnorm[BB];
__device__ float  g_ynorm[VV];
__device__ u64    g_btop[BB][NBLK][BTOP];      // per-(row,block) top-6 keys (1.2 MB)

// Bit-cast __half2 -> uint32_t (toolkit lacks __half2_as_uint)
__device__ __forceinline__ uint32_t h2u(__half2 h) {
    uint32_t u;
    u = *reinterpret_cast<uint32_t*>(&h);
    return u;
}

__device__ __forceinline__ void mma_f16(float c[4],
                                        uint32_t a0, uint32_t a1, uint32_t a2, uint32_t a3,
                                        uint32_t b0, uint32_t b1) {
    asm volatile(
        "mma.sync.aligned.m16n8k16.row.col.f32.f16.f16.f32 "
        "{%0,%1,%2,%3}, {%4,%5,%6,%7}, {%8,%9}, {%0,%1,%2,%3};"
        : "+f"(c[0]), "+f"(c[1]), "+f"(c[2]), "+f"(c[3])
        : "r"(a0), "r"(a1), "r"(a2), "r"(a3), "r"(b0), "r"(b1));
}

// Pack 8 fp32 -> 8 fp16 (rn) as uint4
__device__ __forceinline__ uint4 pack8h(const float4& u, const float4& v) {
    uint4 r;
    r.x = h2u(__float22half2_rn(make_float2(u.x, u.y)));
    r.y = h2u(__float22half2_rn(make_float2(u.z, u.w)));
    r.z = h2u(__float22half2_rn(make_float2(v.x, v.y)));
    r.w = h2u(__float22half2_rn(make_float2(v.z, v.w)));
    return r;
}

// Orderable float <-> uint mapping (total order matching float compare)
__device__ __forceinline__ unsigned int ford(float f) {
    unsigned int u = __float_as_uint(f);
    return (u & 0x80000000u) ? ~u : (u | 0x80000000u);
}
__device__ __forceinline__ float funord(unsigned int r) {
    unsigned int u = (r & 0x80000000u) ? (r & 0x7FFFFFFFu) : ~r;
    return __uint_as_float(u);
}

// key = (orderable(value) << 32) | (VV-1-v): bigger = better, tie -> lower idx
__device__ __forceinline__ u64 mkkey(float val, int v) {
    return ((u64)ford(val) << 32) | (unsigned)(VV - 1 - v);
}
__device__ __forceinline__ int key2idx(u64 k) {
    return VV - 1 - (int)(unsigned)(k & 0xFFFFFFFFu);
}

// Insert x into sorted-descending K-array (drop smallest)
template <int K>
__device__ __forceinline__ void insK(u64 c[K], u64 x) {
    if (x <= c[K - 1]) return;
    c[K - 1] = x;
    #pragma unroll
    for (int i = K - 2; i >= 0; i--) {
        if (c[i + 1] > c[i]) {
            u64 t = c[i]; c[i] = c[i + 1]; c[i + 1] = t;
        }
    }
}

// ---------------------------------------------------------------------------
// Kernel 1: mean-pool partial sums. grid=(NCHUNK, BB), block=256 (float4 each)
// ---------------------------------------------------------------------------
__global__ void __launch_bounds__(256) mean_partial_kernel(const float* __restrict__ patch) {
    int t = threadIdx.x;
    int c = blockIdx.x;
    int b = blockIdx.y;
    const float4* p = reinterpret_cast<const float4*>(
                          patch + ((size_t)b * LL + (size_t)c * LPC) * DD) + t;
    float4 s = make_float4(0.f, 0.f, 0.f, 0.f);
    #pragma unroll 8
    for (int l = 0; l < LPC; l++) {
        float4 v = p[(size_t)l * (DD / 4)];
        s.x += v.x; s.y += v.y; s.z += v.z; s.w += v.w;
    }
    g_part[c][b][t] = s;
}

// ---------------------------------------------------------------------------
// Kernel 2: finalize mean, write exact fp32 + fp16 ts, x norms. grid=BB,block=256
// ---------------------------------------------------------------------------
__global__ void __launch_bounds__(256) finalize_kernel() {
    int b = blockIdx.x;
    int t = threadIdx.x;
    float4 s = make_float4(0.f, 0.f, 0.f, 0.f);
    #pragma unroll
    for (int c = 0; c < NCHUNK; c++) {
        float4 v = g_part[c][b][t];
        s.x += v.x; s.y += v.y; s.z += v.z; s.w += v.w;
    }
    const float inv = 1.0f / (float)LL;
    s.x *= inv; s.y *= inv; s.z *= inv; s.w *= inv;
    reinterpret_cast<float4*>(g_tse[b])[t] = s;
    uint2 h;
    h.x = h2u(__float22half2_rn(make_float2(s.x, s.y)));
    h.y = h2u(__float22half2_rn(make_float2(s.z, s.w)));
    reinterpret_cast<uint2*>(g_ts16[b])[t] = h;

    float ss = s.x * s.x + s.y * s.y + s.z * s.z + s.w * s.w;
    #pragma unroll
    for (int o = 16; o; o >>= 1) ss += __shfl_xor_sync(0xFFFFFFFFu, ss, o);
    __shared__ float red[8];
    if ((t & 31) == 0) red[t >> 5] = ss;
    __syncthreads();
    if (t == 0) {
        float tot = 0.f;
        #pragma unroll
        for (int w = 0; w < 8; w++) tot += red[w];
        g_xnorm[b] = sqrtf(tot);
    }
}

// ---------------------------------------------------------------------------
// Kernel 3: fp16 tensor-core similarity GEMM (m16n8k16, fp32 accum) + fused
// y-norms + fused per-block top-6. Double-buffered smem. grid=NBLK, block=256.
// ---------------------------------------------------------------------------
__global__ void __launch_bounds__(256, 2) gemm_kernel(const float* __restrict__ lex,
                                                      float* __restrict__ out_sim) {
    extern __shared__ char smem8[];
    __half* As  = reinterpret_cast<__half*>(smem8);             // [2][64*KPADH]
    __half* Bs  = reinterpret_cast<__half*>(smem8 + OFS_BS);    // [2][128*KPADH]
    float* s_xn = reinterpret_cast<float*>(smem8 + OFS_XN);     // [64]
    float* s_yn = reinterpret_cast<float*>(smem8 + OFS_YN);     // [128]
    float* Cs   = reinterpret_cast<float*>(smem8);              // overlay [64][CSPAD]
    u64*   tmp  = reinterpret_cast<u64*>(smem8 + OFS_TMP);      // overlay [256][BTOP]

    int tid = threadIdx.x;
    int v0 = blockIdx.x * TNB;
    int lane = tid & 31, wid = tid >> 5;
    int g = lane >> 2, t4 = lane & 3;
    int m_base = (wid >> 2) * 32;
    int n_base = (wid & 3) * 32;

    if (tid < BB) s_xn[tid] = g_xnorm[tid];

    // Loader coords: 16B chunks of 8 halves
    const int arow = tid >> 2;             // 0..63
    const int akq  = (tid & 3) * 8;        // halves
    const int brow0 = tid >> 2;            // rows 0..63  (chunk 0)
    const int brow1 = (tid >> 2) + 64;     // rows 64..127 (chunk 1)
    const int bkq  = (tid & 3) * 8;

    float acc[2][4][4];
    #pragma unroll
    for (int mt = 0; mt < 2; mt++)
        #pragma unroll
        for (int nt = 0; nt < 4; nt++)
            #pragma unroll
            for (int r = 0; r < 4; r++) acc[mt][nt][r] = 0.f;
    float ys0 = 0.f, ys1 = 0.f;

    uint4 a_pre;
    float4 b_pre[4];   // 2 chunks x 2 float4

    // ---- prologue: load tile 0 into buffer 0 ----
    a_pre = *reinterpret_cast<const uint4*>(&g_ts16[arow][akq]);
    {
        int va = v0 + brow0, vb = v0 + brow1;
        const float4 z = make_float4(0.f, 0.f, 0.f, 0.f);
        b_pre[0] = (va < VV) ? *reinterpret_cast<const float4*>(&lex[(size_t)va * DD + bkq]) : z;
        b_pre[1] = (va < VV) ? *reinterpret_cast<const float4*>(&lex[(size_t)va * DD + bkq + 4]) : z;
        b_pre[2] = (vb < VV) ? *reinterpret_cast<const float4*>(&lex[(size_t)vb * DD + bkq]) : z;
        b_pre[3] = (vb < VV) ? *reinterpret_cast<const float4*>(&lex[(size_t)vb * DD + bkq + 4]) : z;
    }
    {
        *reinterpret_cast<uint4*>(&As[arow * KPADH + akq]) = a_pre;
        ys0 += b_pre[0].x*b_pre[0].x + b_pre[0].y*b_pre[0].y + b_pre[0].z*b_pre[0].z + b_pre[0].w*b_pre[0].w
             + b_pre[1].x*b_pre[1].x + b_pre[1].y*b_pre[1].y + b_pre[1].z*b_pre[1].z + b_pre[1].w*b_pre[1].w;
        ys1 += b_pre[2].x*b_pre[2].x + b_pre[2].y*b_pre[2].y + b_pre[2].z*b_pre[2].z + b_pre[2].w*b_pre[2].w
             + b_pre[3].x*b_pre[3].x + b_pre[3].y*b_pre[3].y + b_pre[3].z*b_pre[3].z + b_pre[3].w*b_pre[3].w;
        *reinterpret_cast<uint4*>(&Bs[brow0 * KPADH + bkq]) = pack8h(b_pre[0], b_pre[1]);
        *reinterpret_cast<uint4*>(&Bs[brow1 * KPADH + bkq]) = pack8h(b_pre[2], b_pre[3]);
    }
    __syncthreads();

    const int NIT = DD / TKH;  // 32
    for (int it = 0; it < NIT; it++) {
        int cur = it & 1;
        // ---- prefetch next tile ----
        if (it < NIT - 1) {
            int k0 = (it + 1) * TKH;
            a_pre = *reinterpret_cast<const uint4*>(&g_ts16[arow][k0 + akq]);
            int va = v0 + brow0, vb = v0 + brow1;
            const float4 z = make_float4(0.f, 0.f, 0.f, 0.f);
            b_pre[0] = (va < VV) ? *reinterpret_cast<const float4*>(&lex[(size_t)va * DD + k0 + bkq]) : z;
            b_pre[1] = (va < VV) ? *reinterpret_cast<const float4*>(&lex[(size_t)va * DD + k0 + bkq + 4]) : z;
            b_pre[2] = (vb < VV) ? *reinterpret_cast<const float4*>(&lex[(size_t)vb * DD + k0 + bkq]) : z;
            b_pre[3] = (vb < VV) ? *reinterpret_cast<const float4*>(&lex[(size_t)vb * DD + k0 + bkq + 4]) : z;
        }
        // ---- compute on current buffer ----
        {
            const __half* Ab = As + cur * 64 * KPADH;
            const __half* Bb = Bs + cur * 128 * KPADH;
            #pragma unroll
            for (int ks = 0; ks < 2; ks++) {
                int kb = ks * 16 + 2 * t4;
                uint32_t a[2][4], bf[4][2];
                #pragma unroll
                for (int mt = 0; mt < 2; mt++) {
                    int r0 = m_base + 16 * mt + g;
                    a[mt][0] = *reinterpret_cast<const uint32_t*>(&Ab[r0 * KPADH + kb]);
                    a[mt][1] = *reinterpret_cast<const uint32_t*>(&Ab[(r0 + 8) * KPADH + kb]);
                    a[mt][2] = *reinterpret_cast<const uint32_t*>(&Ab[r0 * KPADH + kb + 8]);
                    a[mt][3] = *reinterpret_cast<const uint32_t*>(&Ab[(r0 + 8) * KPADH + kb + 8]);
                }
                #pragma unroll
                for (int nt = 0; nt < 4; nt++) {
                    int c0 = n_base + 8 * nt + g;
                    bf[nt][0] = *reinterpret_cast<const uint32_t*>(&Bb[c0 * KPADH + kb]);
                    bf[nt][1] = *reinterpret_cast<const uint32_t*>(&Bb[c0 * KPADH + kb + 8]);
                }
                #pragma unroll
                for (int mt = 0; mt < 2; mt++)
                    #pragma unroll
                    for (int nt = 0; nt < 4; nt++)
                        mma_f16(acc[mt][nt], a[mt][0], a[mt][1], a[mt][2], a[mt][3],
                                bf[nt][0], bf[nt][1]);
            }
        }
        // ---- store prefetched tile into other buffer ----
        if (it < NIT - 1) {
            __half* Ab = As + (1 - cur) * 64 * KPADH;
            __half* Bb = Bs + (1 - cur) * 128 * KPADH;
            *reinterpret_cast<uint4*>(&Ab[arow * KPADH + akq]) = a_pre;
            ys0 += b_pre[0].x*b_pre[0].x + b_pre[0].y*b_pre[0].y + b_pre[0].z*b_pre[0].z + b_pre[0].w*b_pre[0].w
                 + b_pre[1].x*b_pre[1].x + b_pre[1].y*b_pre[1].y + b_pre[1].z*b_pre[1].z + b_pre[1].w*b_pre[1].w;
            ys1 += b_pre[2].x*b_pre[2].x + b_pre[2].y*b_pre[2].y + b_pre[2].z*b_pre[2].z + b_pre[2].w*b_pre[2].w
                 + b_pre[3].x*b_pre[3].x + b_pre[3].y*b_pre[3].y + b_pre[3].z*b_pre[3].z + b_pre[3].w*b_pre[3].w;
            *reinterpret_cast<uint4*>(&Bb[brow0 * KPADH + bkq]) = pack8h(b_pre[0], b_pre[1]);
            *reinterpret_cast<uint4*>(&Bb[brow1 * KPADH + bkq]) = pack8h(b_pre[2], b_pre[3]);
            __syncthreads();
        }
    }

    // ---- y norms: reduce over the 4 threads (quad) sharing each row ----
    ys0 += __shfl_down_sync(0xFFFFFFFFu, ys0, 2, 4);
    ys0 += __shfl_down_sync(0xFFFFFFFFu, ys0, 1, 4);
    ys1 += __shfl_down_sync(0xFFFFFFFFu, ys1, 2, 4);
    ys1 += __shfl_down_sync(0xFFFFFFFFu, ys1, 1, 4);
    if ((tid & 3) == 0) {
        int n = tid >> 2;
        float yn0 = sqrtf(ys0), yn1 = sqrtf(ys1);
        s_yn[n] = yn0;
        s_yn[n + 64] = yn1;
        if (v0 + n < VV) g_ynorm[v0 + n] = yn0;
        if (v0 + n + 64 < VV) g_ynorm[v0 + n + 64] = yn1;
    }
    __syncthreads();  // all warps done with As/Bs; s_yn ready; overlay begins

    // ---- stage normalized tile in smem (Cs overlays As/Bs) ----
    #pragma unroll
    for (int mt = 0; mt < 2; mt++) {
        int m0 = m_base + 16 * mt + g;
        float xn0 = s_xn[m0], xn1 = s_xn[m0 + 8];
        #pragma unroll
        for (int nt = 0; nt < 4; nt++) {
            int ncol = n_base + 8 * nt + 2 * t4;
            #pragma unroll
            for (int j = 0; j < 2; j++) {
                int v = v0 + ncol + j;
                float yn = s_yn[ncol + j];
                float s0 = acc[mt][nt][j]     / fmaxf(xn0 * yn, 1e-8f);
                float s1 = acc[mt][nt][2 + j] / fmaxf(xn1 * yn, 1e-8f);
                if (v >= VV) { s0 = -3.4e38f; s1 = -3.4e38f; }
                Cs[m0 * CSPAD + ncol + j]       = s0;
                Cs[(m0 + 8) * CSPAD + ncol + j] = s1;
            }
        }
    }
    __syncthreads();

    // ---- coalesced out_sim write ----
    #pragma unroll
    for (int i = 0; i < 32; i++) {
        int idx = tid + i * 256;
        int m = idx >> 7, col = idx & 127;
        int v = v0 + col;
        if (v < VV)
            out_sim[(size_t)m * VV + v] = Cs[m * CSPAD + col];
    }

    // ---- per-row top-6: 4 threads/row, 32 cols each ----
    {
        int row = tid >> 2, q = tid & 3;
        u64 t6[BTOP] = {0, 0, 0, 0, 0, 0};
        #pragma unroll
        for (int i = 0; i < 32; i++) {
            int col = q * 32 + i;
            int v = v0 + col;
            if (v < VV) insK<BTOP>(t6, mkkey(Cs[row * CSPAD + col], v));
        }
        #pragma unroll
        for (int i = 0; i < BTOP; i++) tmp[tid * BTOP + i] = t6[i];
    }
    __syncthreads();
    if (tid < BB) {
        u64 t6[BTOP] = {0, 0, 0, 0, 0, 0};
        #pragma unroll
        for (int q = 0; q < 4; q++)
            #pragma unroll
            for (int i = 0; i < BTOP; i++)
                insK<BTOP>(t6, tmp[(tid * 4 + q) * BTOP + i]);
        #pragma unroll
        for (int i = 0; i < BTOP; i++) g_btop[tid][blockIdx.x][i] = t6[i];
    }
}

// ---------------------------------------------------------------------------
// Kernel 4: merge per-block top-6 keys -> approx top-5 -> threshold candidates
// -> exact fp32 recompute -> exact select -> gather. grid=BB, block=512.
// ---------------------------------------------------------------------------
__global__ void __launch_bounds__(512) merge_kernel(const float* __restrict__ lex,
                                                    float* __restrict__ out_topk) {
    int b = blockIdx.x;
    int t = threadIdx.x;
    int lane = t & 31, wid = t >> 5;

    __shared__ u64   wtop[16][5];
    __shared__ float s_thresh;
    __shared__ int   cand[NCAND];
    __shared__ float cval[NCAND];
    __shared__ int   ncand;
    __shared__ int   selci[TOPK];
    __shared__ int   selfin[TOPK];

    const u64* keys = &g_btop[b][0][0];
    const int NK = NBLK * BTOP;  // 2358

    // Phase A: block-wide top-5 over keys
    u64 t5[5] = {0, 0, 0, 0, 0};
    for (int i = t; i < NK; i += 512) insK<5>(t5, keys[i]);
    #pragma unroll
    for (int o = 16; o; o >>= 1) {
        u64 ot[5];
        #pragma unroll
        for (int i = 0; i < 5; i++) ot[i] = __shfl_xor_sync(0xFFFFFFFFu, t5[i], o);
        #pragma unroll
        for (int i = 0; i < 5; i++) insK<5>(t5, ot[i]);
    }
    if (lane == 0) {
        #pragma unroll
        for (int i = 0; i < 5; i++) wtop[wid][i] = t5[i];
    }
    __syncthreads();
    if (wid == 0) {
        const u64* flat = &wtop[0][0];  // 80 keys
        u64 m5[5] = {0, 0, 0, 0, 0};
        insK<5>(m5, flat[lane]);
        insK<5>(m5, flat[lane + 32]);
        if (lane < 16) insK<5>(m5, flat[lane + 64]);
        #pragma unroll
        for (int o = 16; o; o >>= 1) {
            u64 ot[5];
            #pragma unroll
            for (int i = 0; i < 5; i++) ot[i] = __shfl_xor_sync(0xFFFFFFFFu, m5[i], o);
            #pragma unroll
            for (int i = 0; i < 5; i++) insK<5>(m5, ot[i]);
        }
        if (lane == 0) {
            s_thresh = funord((unsigned)(m5[4] >> 32)) - 5e-4f;
            ncand = 0;
        }
    }
    __syncthreads();

    // Phase B: candidates = keys with value >= thresh (unique by construction)
    float thr = s_thresh;
    for (int i = t; i < NK; i += 512) {
        u64 k = keys[i];
        if (funord((unsigned)(k >> 32)) >= thr) {
            int slot = atomicAdd(&ncand, 1);
            if (slot < NCAND) cand[slot] = key2idx(k);
        }
    }
    __syncthreads();
    int nc = min(ncand, NCAND);

    // Phase C: exact fp32 recompute (one warp per candidate, 16 warps)
    {
        const float4* ts4 = reinterpret_cast<const float4*>(g_tse[b]);
        for (int ci = wid; ci < nc; ci += 16) {
            int v = cand[ci];
            const float4* lx4 = reinterpret_cast<const float4*>(lex + (size_t)v * DD);
            float d = 0.f;
            #pragma unroll
            for (int j = 0; j < 8; j++) {
                float4 a = ts4[j * 32 + lane];
                float4 c = lx4[j * 32 + lane];
                d += a.x * c.x + a.y * c.y + a.z * c.z + a.w * c.w;
            }
            #pragma unroll
            for (int o = 16; o; o >>= 1) d += __shfl_xor_sync(0xFFFFFFFFu, d, o);
            if (lane == 0)
                cval[ci] = d / fmaxf(g_xnorm[b] * g_ynorm[v], 1e-8f);
        }
    }
    __syncthreads();

    // Phase D: exact top-5 over candidates (warp 0), tie-break lowest index
    if (t < 32) {
        for (int j = 0; j < TOPK; j++) {
            float bv = -1e30f;
            int bvi = 0x7FFFFFFF;
            int bci = -1;
            for (int ci = t; ci < nc; ci += 32) {
                bool used = false;
                #pragma unroll
                for (int jj = 0; jj < TOPK; jj++)
                    if (jj < j && selci[jj] == ci) used = true;
                if (used) continue;
                float x = cval[ci];
                int v = cand[ci];
                if (x > bv || (x == bv && v < bvi)) { bv = x; bvi = v; bci = ci; }
            }
            #pragma unroll
            for (int o = 16; o; o >>= 1) {
                float ov  = __shfl_xor_sync(0xFFFFFFFFu, bv, o);
                int   ovi = __shfl_xor_sync(0xFFFFFFFFu, bvi, o);
                int   oci = __shfl_xor_sync(0xFFFFFFFFu, bci, o);
                if (ov > bv || (ov == bv && ovi < bvi)) { bv = ov; bvi = ovi; bci = oci; }
            }
            if (t == 0) { selci[j] = bci; selfin[j] = bvi; }
            __syncwarp();
        }
    }
    __syncthreads();

    // Phase E: gather top-k lexicon rows
    for (int j = 0; j < TOPK; j++) {
        const float4* src = reinterpret_cast<const float4*>(lex + (size_t)selfin[j] * DD);
        float4* dst = reinterpret_cast<float4*>(out_topk + ((size_t)b * TOPK + j) * DD);
        if (t < DD / 4) dst[t] = src[t];
    }
}

// ---------------------------------------------------------------------------
extern "C" void kernel_launch(void* const* d_in, const int* in_sizes, int n_in,
                              void* d_out, int out_size) {
    const float* patch = (const float*)d_in[0];
    const float* lex   = (const float*)d_in[1];
    float* out      = (float*)d_out;
    float* out_topk = out;                                  // [64][5][1024]
    float* out_sim  = out + (size_t)BB * TOPK * DD;         // [64][50257]

    cudaFuncSetAttribute(gemm_kernel, cudaFuncAttributeMaxDynamicSharedMemorySize,
                         GEMM_SMEM);

    mean_partial_kernel<<<dim3(NCHUNK, BB), 256>>>(patch);
    finalize_kernel<<<BB, 256>>>();
    gemm_kernel<<<NBLK, 256, GEMM_SMEM>>>(lex, out_sim);
    merge_kernel<<<BB, 512>>>(lex, out_topk);
}

// round 8
// speedup vs baseline: 1.0244x; 1.0244x over previous
#include <cuda_runtime.h>
#include <cuda_bf16.h>
#include <cuda_fp16.h>
#include <math.h>
#include <cstdint>

// Problem dims (fixed for this bench)
#define BB 64
#define LL 2048
#define DD 1024
#define VV 50257
#define TOPK 5

#define NCHUNK 16
#define LPC (LL / NCHUNK)        // 128 rows per chunk

#define TNB 128                  // GEMM N tile
#define NBLK ((VV + TNB - 1) / TNB)   // 393
#define TKH 32                   // GEMM K tile (fp16 elements)
#define KPADH 40                 // padded k stride in halves (80B rows: LDSM conflict-free)
#define NCAND 64
#define BTOP 6                   // per-block-per-row top-K kept
#define CSPAD 129                // Cs row stride (floats)

// Smem blob layout (bytes):
//   [0 .. 10240)            As: 2 bufs x 64 x KPADH halves
//   [10240 .. 30720)        Bs: 2 bufs x 128 x KPADH halves
//   -- epilogue overlay on [0 .. 45312):
//   [0 .. 33024)            Cs: 64 x CSPAD floats
//   [33024 .. 45312)        tmp: 256 x BTOP u64
//   [45312 .. 45568)        s_xn: 64 floats
//   [45568 .. 46080)        s_yn: 128 floats
#define OFS_BS   10240
#define OFS_TMP  33024
#define OFS_XN   45312
#define OFS_YN   45568
#define GEMM_SMEM 46080

typedef unsigned long long u64;

// Scratch (device globals; no allocations allowed)
__device__ float4 g_part[NCHUNK][BB][DD / 4];  // mean-pool partials (4 MB)
__device__ float  g_tse[BB][DD];               // exact fp32 pooled embeddings
__device__ __half g_ts16[BB][DD];              // fp16 pooled embeddings (mma operand)
__device__ float  g_xnorm[BB];
__device__ float  g_ynorm[VV];
__device__ u64    g_btop[BB][NBLK][BTOP];      // per-(row,block) top-6 keys (1.2 MB)

// Bit-cast __half2 -> uint32_t
__device__ __forceinline__ uint32_t h2u(__half2 h) {
    return *reinterpret_cast<uint32_t*>(&h);
}

__device__ __forceinline__ void mma_f16(float c[4],
                                        uint32_t a0, uint32_t a1, uint32_t a2, uint32_t a3,
                                        uint32_t b0, uint32_t b1) {
    asm volatile(
        "mma.sync.aligned.m16n8k16.row.col.f32.f16.f16.f32 "
        "{%0,%1,%2,%3}, {%4,%5,%6,%7}, {%8,%9}, {%0,%1,%2,%3};"
        : "+f"(c[0]), "+f"(c[1]), "+f"(c[2]), "+f"(c[3])
        : "r"(a0), "r"(a1), "r"(a2), "r"(a3), "r"(b0), "r"(b1));
}

__device__ __forceinline__ void ldsm4(uint32_t& r0, uint32_t& r1, uint32_t& r2, uint32_t& r3,
                                      uint32_t addr) {
    asm volatile("ldmatrix.sync.aligned.m8n8.x4.shared.b16 {%0,%1,%2,%3}, [%4];"
                 : "=r"(r0), "=r"(r1), "=r"(r2), "=r"(r3) : "r"(addr));
}

// Orderable float <-> uint mapping (total order matching float compare)
__device__ __forceinline__ unsigned int ford(float f) {
    unsigned int u = __float_as_uint(f);
    return (u & 0x80000000u) ? ~u : (u | 0x80000000u);
}
__device__ __forceinline__ float funord(unsigned int r) {
    unsigned int u = (r & 0x80000000u) ? (r & 0x7FFFFFFFu) : ~r;
    return __uint_as_float(u);
}

// key = (orderable(value) << 32) | (VV-1-v): bigger = better, tie -> lower idx
__device__ __forceinline__ u64 mkkey(float val, int v) {
    return ((u64)ford(val) << 32) | (unsigned)(VV - 1 - v);
}
__device__ __forceinline__ int key2idx(u64 k) {
    return VV - 1 - (int)(unsigned)(k & 0xFFFFFFFFu);
}

// Insert x into sorted-descending K-array (drop smallest)
template <int K>
__device__ __forceinline__ void insK(u64 c[K], u64 x) {
    if (x <= c[K - 1]) return;
    c[K - 1] = x;
    #pragma unroll
    for (int i = K - 2; i >= 0; i--) {
        if (c[i + 1] > c[i]) {
            u64 t = c[i]; c[i] = c[i + 1]; c[i + 1] = t;
        }
    }
}

// ---------------------------------------------------------------------------
// Kernel 1: mean-pool partial sums. grid=(NCHUNK, BB), block=256 (float4 each)
// ---------------------------------------------------------------------------
__global__ void __launch_bounds__(256) mean_partial_kernel(const float* __restrict__ patch) {
    int t = threadIdx.x;
    int c = blockIdx.x;
    int b = blockIdx.y;
    const float4* p = reinterpret_cast<const float4*>(
                          patch + ((size_t)b * LL + (size_t)c * LPC) * DD) + t;
    float4 s = make_float4(0.f, 0.f, 0.f, 0.f);
    #pragma unroll 8
    for (int l = 0; l < LPC; l++) {
        float4 v = p[(size_t)l * (DD / 4)];
        s.x += v.x; s.y += v.y; s.z += v.z; s.w += v.w;
    }
    g_part[c][b][t] = s;
}

// ---------------------------------------------------------------------------
// Kernel 2: finalize mean, write exact fp32 + fp16 ts, x norms. grid=BB,block=256
// ---------------------------------------------------------------------------
__global__ void __launch_bounds__(256) finalize_kernel() {
    int b = blockIdx.x;
    int t = threadIdx.x;
    float4 s = make_float4(0.f, 0.f, 0.f, 0.f);
    #pragma unroll
    for (int c = 0; c < NCHUNK; c++) {
        float4 v = g_part[c][b][t];
        s.x += v.x; s.y += v.y; s.z += v.z; s.w += v.w;
    }
    const float inv = 1.0f / (float)LL;
    s.x *= inv; s.y *= inv; s.z *= inv; s.w *= inv;
    reinterpret_cast<float4*>(g_tse[b])[t] = s;
    uint2 h;
    h.x = h2u(__float22half2_rn(make_float2(s.x, s.y)));
    h.y = h2u(__float22half2_rn(make_float2(s.z, s.w)));
    reinterpret_cast<uint2*>(g_ts16[b])[t] = h;

    float ss = s.x * s.x + s.y * s.y + s.z * s.z + s.w * s.w;
    #pragma unroll
    for (int o = 16; o; o >>= 1) ss += __shfl_xor_sync(0xFFFFFFFFu, ss, o);
    __shared__ float red[8];
    if ((t & 31) == 0) red[t >> 5] = ss;
    __syncthreads();
    if (t == 0) {
        float tot = 0.f;
        #pragma unroll
        for (int w = 0; w < 8; w++) tot += red[w];
        g_xnorm[b] = sqrtf(tot);
    }
}

// ---------------------------------------------------------------------------
// Kernel 3: fp16 tensor-core similarity GEMM (m16n8k16, fp32 accum) + fused
// y-norms + fused per-block top-6. Double-buffered smem, ldmatrix fragment
// loads, full-line coalesced B LDGs. grid=NBLK, block=256.
// ---------------------------------------------------------------------------
__global__ void __launch_bounds__(256, 2) gemm_kernel(const float* __restrict__ lex,
                                                      float* __restrict__ out_sim) {
    extern __shared__ char smem8[];
    __half* As  = reinterpret_cast<__half*>(smem8);             // [2][64*KPADH]
    __half* Bs  = reinterpret_cast<__half*>(smem8 + OFS_BS);    // [2][128*KPADH]
    float* s_xn = reinterpret_cast<float*>(smem8 + OFS_XN);     // [64]
    float* s_yn = reinterpret_cast<float*>(smem8 + OFS_YN);     // [128]
    float* Cs   = reinterpret_cast<float*>(smem8);              // overlay [64][CSPAD]
    u64*   tmp  = reinterpret_cast<u64*>(smem8 + OFS_TMP);      // overlay [256][BTOP]

    int tid = threadIdx.x;
    int v0 = blockIdx.x * TNB;
    int lane = tid & 31, wid = tid >> 5;
    int g = lane >> 2, t4 = lane & 3;
    int m_base = (wid >> 2) * 32;
    int n_base = (wid & 3) * 32;

    if (tid < BB) s_xn[tid] = g_xnorm[tid];

    // ldmatrix per-lane byte offsets (row stride = 80B; conflict-free phases)
    const uint32_t smem_u32 = (uint32_t)__cvta_generic_to_shared(smem8);
    const uint32_t As_u32 = smem_u32;
    const uint32_t Bs_u32 = smem_u32 + OFS_BS;
    const int a_moff = (((lane >> 3) & 1) << 3) + (lane & 7);   // row within 16
    const int a_khi  = (lane >> 4) << 4;                        // +16B for k-high half
    const uint32_t a_lane_off = (uint32_t)((m_base + a_moff) * 80 + a_khi);
    const int b_noff = ((lane >> 4) << 3) + (lane & 7);         // row within 16 (nt pair)
    const int b_k8   = (((lane >> 3) & 1) << 4);                // +16B for k+8
    const uint32_t b_lane_off = (uint32_t)((n_base + b_noff) * 80 + b_k8);

    // A loader coords (16B of 8 halves per thread)
    const int arow = tid >> 2;
    const int akq  = (tid & 3) * 8;        // halves
    // B loader coords: 8 threads per row, 1 float4 each; 4 row-passes
    const int brow = tid >> 3;             // 0..31 (+32*i)
    const int bkqf = (tid & 7) * 4;        // floats
    const int bkqh = (tid & 7) * 4;        // halves (after fp16 pack: 4 halves = 8B)

    float acc[2][4][4];
    #pragma unroll
    for (int mt = 0; mt < 2; mt++)
        #pragma unroll
        for (int nt = 0; nt < 4; nt++)
            #pragma unroll
            for (int r = 0; r < 4; r++) acc[mt][nt][r] = 0.f;
    float yacc[4] = {0.f, 0.f, 0.f, 0.f};

    uint4 a_pre;
    float4 b_pre[4];

    // ---- prologue: load tile 0 into buffer 0 ----
    a_pre = *reinterpret_cast<const uint4*>(&g_ts16[arow][akq]);
    #pragma unroll
    for (int i = 0; i < 4; i++) {
        int v = v0 + brow + 32 * i;
        b_pre[i] = (v < VV)
            ? *reinterpret_cast<const float4*>(&lex[(size_t)v * DD + bkqf])
            : make_float4(0.f, 0.f, 0.f, 0.f);
    }
    {
        *reinterpret_cast<uint4*>(&As[arow * KPADH + akq]) = a_pre;
        #pragma unroll
        for (int i = 0; i < 4; i++) {
            float4 w = b_pre[i];
            yacc[i] += w.x * w.x + w.y * w.y + w.z * w.z + w.w * w.w;
            uint2 st;
            st.x = h2u(__float22half2_rn(make_float2(w.x, w.y)));
            st.y = h2u(__float22half2_rn(make_float2(w.z, w.w)));
            *reinterpret_cast<uint2*>(&Bs[(brow + 32 * i) * KPADH + bkqh]) = st;
        }
    }
    __syncthreads();

    const int NIT = DD / TKH;  // 32
    for (int it = 0; it < NIT; it++) {
        int cur = it & 1;
        // ---- prefetch next tile ----
        if (it < NIT - 1) {
            int k0 = (it + 1) * TKH;
            a_pre = *reinterpret_cast<const uint4*>(&g_ts16[arow][k0 + akq]);
            #pragma unroll
            for (int i = 0; i < 4; i++) {
                int v = v0 + brow + 32 * i;
                b_pre[i] = (v < VV)
                    ? *reinterpret_cast<const float4*>(&lex[(size_t)v * DD + k0 + bkqf])
                    : make_float4(0.f, 0.f, 0.f, 0.f);
            }
        }
        // ---- compute on current buffer (ldmatrix fragments) ----
        {
            const uint32_t Acur = As_u32 + (uint32_t)(cur * 64 * 80);
            const uint32_t Bcur = Bs_u32 + (uint32_t)(cur * 128 * 80);
            #pragma unroll
            for (int ks = 0; ks < 2; ks++) {
                uint32_t a[2][4], bf[4][2];
                #pragma unroll
                for (int mt = 0; mt < 2; mt++)
                    ldsm4(a[mt][0], a[mt][1], a[mt][2], a[mt][3],
                          Acur + a_lane_off + (uint32_t)(mt * 16 * 80 + ks * 32));
                #pragma unroll
                for (int p = 0; p < 2; p++)
                    ldsm4(bf[2 * p][0], bf[2 * p][1], bf[2 * p + 1][0], bf[2 * p + 1][1],
                          Bcur + b_lane_off + (uint32_t)(p * 16 * 80 + ks * 32));
                #pragma unroll
                for (int mt = 0; mt < 2; mt++)
                    #pragma unroll
                    for (int nt = 0; nt < 4; nt++)
                        mma_f16(acc[mt][nt], a[mt][0], a[mt][1], a[mt][2], a[mt][3],
                                bf[nt][0], bf[nt][1]);
            }
        }
        // ---- store prefetched tile into other buffer ----
        if (it < NIT - 1) {
            __half* Ab = As + (1 - cur) * 64 * KPADH;
            __half* Bb = Bs + (1 - cur) * 128 * KPADH;
            *reinterpret_cast<uint4*>(&Ab[arow * KPADH + akq]) = a_pre;
            #pragma unroll
            for (int i = 0; i < 4; i++) {
                float4 w = b_pre[i];
                yacc[i] += w.x * w.x + w.y * w.y + w.z * w.z + w.w * w.w;
                uint2 st;
                st.x = h2u(__float22half2_rn(make_float2(w.x, w.y)));
                st.y = h2u(__float22half2_rn(make_float2(w.z, w.w)));
                *reinterpret_cast<uint2*>(&Bb[(brow + 32 * i) * KPADH + bkqh]) = st;
            }
            __syncthreads();
        }
    }

    // ---- y norms: reduce over the 8 threads sharing each row ----
    #pragma unroll
    for (int i = 0; i < 4; i++) {
        float ys = yacc[i];
        ys += __shfl_down_sync(0xFFFFFFFFu, ys, 4, 8);
        ys += __shfl_down_sync(0xFFFFFFFFu, ys, 2, 8);
        ys += __shfl_down_sync(0xFFFFFFFFu, ys, 1, 8);
        if ((tid & 7) == 0) {
            int n = brow + 32 * i;
            float yn = sqrtf(ys);
            s_yn[n] = yn;
            if (v0 + n < VV) g_ynorm[v0 + n] = yn;
        }
    }
    __syncthreads();  // all warps done with As/Bs; s_yn ready; overlay begins

    // ---- stage normalized tile in smem (Cs overlays As/Bs) ----
    #pragma unroll
    for (int mt = 0; mt < 2; mt++) {
        int m0 = m_base + 16 * mt + g;
        float xn0 = s_xn[m0], xn1 = s_xn[m0 + 8];
        #pragma unroll
        for (int nt = 0; nt < 4; nt++) {
            int ncol = n_base + 8 * nt + 2 * t4;
            #pragma unroll
            for (int j = 0; j < 2; j++) {
                int v = v0 + ncol + j;
                float yn = s_yn[ncol + j];
                float s0 = acc[mt][nt][j]     / fmaxf(xn0 * yn, 1e-8f);
                float s1 = acc[mt][nt][2 + j] / fmaxf(xn1 * yn, 1e-8f);
                if (v >= VV) { s0 = -3.4e38f; s1 = -3.4e38f; }
                Cs[m0 * CSPAD + ncol + j]       = s0;
                Cs[(m0 + 8) * CSPAD + ncol + j] = s1;
            }
        }
    }
    __syncthreads();

    // ---- coalesced out_sim write ----
    #pragma unroll
    for (int i = 0; i < 32; i++) {
        int idx = tid + i * 256;
        int m = idx >> 7, col = idx & 127;
        int v = v0 + col;
        if (v < VV)
            out_sim[(size_t)m * VV + v] = Cs[m * CSPAD + col];
    }

    // ---- per-row top-6: 4 threads/row, 32 cols each ----
    {
        int row = tid >> 2, q = tid & 3;
        u64 t6[BTOP] = {0, 0, 0, 0, 0, 0};
        #pragma unroll
        for (int i = 0; i < 32; i++) {
            int col = q * 32 + i;
            int v = v0 + col;
            if (v < VV) insK<BTOP>(t6, mkkey(Cs[row * CSPAD + col], v));
        }
        #pragma unroll
        for (int i = 0; i < BTOP; i++) tmp[tid * BTOP + i] = t6[i];
    }
    __syncthreads();
    if (tid < BB) {
        u64 t6[BTOP] = {0, 0, 0, 0, 0, 0};
        #pragma unroll
        for (int q = 0; q < 4; q++)
            #pragma unroll
            for (int i = 0; i < BTOP; i++)
                insK<BTOP>(t6, tmp[(tid * 4 + q) * BTOP + i]);
        #pragma unroll
        for (int i = 0; i < BTOP; i++) g_btop[tid][blockIdx.x][i] = t6[i];
    }
}

// ---------------------------------------------------------------------------
// Kernel 4: merge per-block top-6 keys -> approx top-5 -> threshold candidates
// -> exact fp32 recompute -> exact select -> gather. grid=BB, block=512.
// ---------------------------------------------------------------------------
__global__ void __launch_bounds__(512) merge_kernel(const float* __restrict__ lex,
                                                    float* __restrict__ out_topk) {
    int b = blockIdx.x;
    int t = threadIdx.x;
    int lane = t & 31, wid = t >> 5;

    __shared__ u64   wtop[16][5];
    __shared__ float s_thresh;
    __shared__ int   cand[NCAND];
    __shared__ float cval[NCAND];
    __shared__ int   ncand;
    __shared__ int   selci[TOPK];
    __shared__ int   selfin[TOPK];

    const u64* keys = &g_btop[b][0][0];
    const int NK = NBLK * BTOP;  // 2358

    // Phase A: block-wide top-5 over keys
    u64 t5[5] = {0, 0, 0, 0, 0};
    for (int i = t; i < NK; i += 512) insK<5>(t5, keys[i]);
    #pragma unroll
    for (int o = 16; o; o >>= 1) {
        u64 ot[5];
        #pragma unroll
        for (int i = 0; i < 5; i++) ot[i] = __shfl_xor_sync(0xFFFFFFFFu, t5[i], o);
        #pragma unroll
        for (int i = 0; i < 5; i++) insK<5>(t5, ot[i]);
    }
    if (lane == 0) {
        #pragma unroll
        for (int i = 0; i < 5; i++) wtop[wid][i] = t5[i];
    }
    __syncthreads();
    if (wid == 0) {
        const u64* flat = &wtop[0][0];  // 80 keys
        u64 m5[5] = {0, 0, 0, 0, 0};
        insK<5>(m5, flat[lane]);
        insK<5>(m5, flat[lane + 32]);
        if (lane < 16) insK<5>(m5, flat[lane + 64]);
        #pragma unroll
        for (int o = 16; o; o >>= 1) {
            u64 ot[5];
            #pragma unroll
            for (int i = 0; i < 5; i++) ot[i] = __shfl_xor_sync(0xFFFFFFFFu, m5[i], o);
            #pragma unroll
            for (int i = 0; i < 5; i++) insK<5>(m5, ot[i]);
        }
        if (lane == 0) {
            s_thresh = funord((unsigned)(m5[4] >> 32)) - 5e-4f;
            ncand = 0;
        }
    }
    __syncthreads();

    // Phase B: candidates = keys with value >= thresh (unique by construction)
    float thr = s_thresh;
    for (int i = t; i < NK; i += 512) {
        u64 k = keys[i];
        if (funord((unsigned)(k >> 32)) >= thr) {
            int slot = atomicAdd(&ncand, 1);
            if (slot < NCAND) cand[slot] = key2idx(k);
        }
    }
    __syncthreads();
    int nc = min(ncand, NCAND);

    // Phase C: exact fp32 recompute (one warp per candidate, 16 warps)
    {
        const float4* ts4 = reinterpret_cast<const float4*>(g_tse[b]);
        for (int ci = wid; ci < nc; ci += 16) {
            int v = cand[ci];
            const float4* lx4 = reinterpret_cast<const float4*>(lex + (size_t)v * DD);
            float d = 0.f;
            #pragma unroll
            for (int j = 0; j < 8; j++) {
                float4 a = ts4[j * 32 + lane];
                float4 c = lx4[j * 32 + lane];
                d += a.x * c.x + a.y * c.y + a.z * c.z + a.w * c.w;
            }
            #pragma unroll
            for (int o = 16; o; o >>= 1) d += __shfl_xor_sync(0xFFFFFFFFu, d, o);
            if (lane == 0)
                cval[ci] = d / fmaxf(g_xnorm[b] * g_ynorm[v], 1e-8f);
        }
    }
    __syncthreads();

    // Phase D: exact top-5 over candidates (warp 0), tie-break lowest index
    if (t < 32) {
        for (int j = 0; j < TOPK; j++) {
            float bv = -1e30f;
            int bvi = 0x7FFFFFFF;
            int bci = -1;
            for (int ci = t; ci < nc; ci += 32) {
                bool used = false;
                #pragma unroll
                for (int jj = 0; jj < TOPK; jj++)
                    if (jj < j && selci[jj] == ci) used = true;
                if (used) continue;
                float x = cval[ci];
                int v = cand[ci];
                if (x > bv || (x == bv && v < bvi)) { bv = x; bvi = v; bci = ci; }
            }
            #pragma unroll
            for (int o = 16; o; o >>= 1) {
                float ov  = __shfl_xor_sync(0xFFFFFFFFu, bv, o);
                int   ovi = __shfl_xor_sync(0xFFFFFFFFu, bvi, o);
                int   oci = __shfl_xor_sync(0xFFFFFFFFu, bci, o);
                if (ov > bv || (ov == bv && ovi < bvi)) { bv = ov; bvi = ovi; bci = oci; }
            }
            if (t == 0) { selci[j] = bci; selfin[j] = bvi; }
            __syncwarp();
        }
    }
    __syncthreads();

    // Phase E: gather top-k lexicon rows
    for (int j = 0; j < TOPK; j++) {
        const float4* src = reinterpret_cast<const float4*>(lex + (size_t)selfin[j] * DD);
        float4* dst = reinterpret_cast<float4*>(out_topk + ((size_t)b * TOPK + j) * DD);
        if (t < DD / 4) dst[t] = src[t];
    }
}

// ---------------------------------------------------------------------------
extern "C" void kernel_launch(void* const* d_in, const int* in_sizes, int n_in,
                              void* d_out, int out_size) {
    const float* patch = (const float*)d_in[0];
    const float* lex   = (const float*)d_in[1];
    float* out      = (float*)d_out;
    float* out_topk = out;                                  // [64][5][1024]
    float* out_sim  = out + (size_t)BB * TOPK * DD;         // [64][50257]

    cudaFuncSetAttribute(gemm_kernel, cudaFuncAttributeMaxDynamicSharedMemorySize,
                         GEMM_SMEM);

    mean_partial_kernel<<<dim3(NCHUNK, BB), 256>>>(patch);
    finalize_kernel<<<BB, 256>>>();
    gemm_kernel<<<NBLK, 256, GEMM_SMEM>>>(lex, out_sim);
    merge_kernel<<<BB, 512>>>(lex, out_topk);
}

// round 10
// speedup vs baseline: 1.0950x; 1.0689x over previous
#include <cuda_runtime.h>
#include <cuda_bf16.h>
#include <cuda_fp16.h>
#include <math.h>
#include <cstdint>

// Problem dims (fixed for this bench)
#define BB 64
#define LL 2048
#define DD 1024
#define VV 50257
#define TOPK 5

#define NCHUNK 16
#define LPC (LL / NCHUNK)        // 128 rows per chunk

#define TNB 128                  // GEMM N tile
#define NBLK ((VV + TNB - 1) / TNB)   // 393
#define TKH 32                   // GEMM K tile (fp16 elements)
#define KPADH 40                 // padded k stride in halves (80B rows: LDSM conflict-free)
#define NCAND 64
#define BTOP 6                   // per-block-per-row top-K kept
#define CSPAD 129                // Cs row stride (floats)

// Smem blob layout (bytes):
//   [0 .. 10240)            As: 2 bufs x 64 x KPADH halves
//   [10240 .. 30720)        Bs: 2 bufs x 128 x KPADH halves
//   -- epilogue overlay on [0 .. 45312):
//   [0 .. 33024)            Cs: 64 x CSPAD floats
//   [33024 .. 45312)        tmp: 256 x BTOP u64
//   [45312 .. 45568)        s_xn: 64 floats
//   [45568 .. 46080)        s_yn: 128 floats
#define OFS_BS   10240
#define OFS_TMP  33024
#define OFS_XN   45312
#define OFS_YN   45568
#define GEMM_SMEM 46080

typedef unsigned long long u64;

// Scratch (device globals; no allocations allowed)
__device__ float4 g_part[NCHUNK][BB][DD / 4];  // mean-pool partials (4 MB)
__device__ float  g_tse[BB][DD];               // exact fp32 pooled embeddings
__device__ __half g_ts16[BB][DD];              // fp16 pooled embeddings (mma operand)
__device__ float  g_xnorm[BB];
__device__ float  g_ynorm[VV];
__device__ u64    g_btop[BB][NBLK][BTOP];      // per-(row,block) top-6 keys (1.2 MB)

// Bit-cast __half2 -> uint32_t
__device__ __forceinline__ uint32_t h2u(__half2 h) {
    return *reinterpret_cast<uint32_t*>(&h);
}

__device__ __forceinline__ void mma_f16(float c[4],
                                        uint32_t a0, uint32_t a1, uint32_t a2, uint32_t a3,
                                        uint32_t b0, uint32_t b1) {
    asm volatile(
        "mma.sync.aligned.m16n8k16.row.col.f32.f16.f16.f32 "
        "{%0,%1,%2,%3}, {%4,%5,%6,%7}, {%8,%9}, {%0,%1,%2,%3};"
        : "+f"(c[0]), "+f"(c[1]), "+f"(c[2]), "+f"(c[3])
        : "r"(a0), "r"(a1), "r"(a2), "r"(a3), "r"(b0), "r"(b1));
}

__device__ __forceinline__ void ldsm4(uint32_t& r0, uint32_t& r1, uint32_t& r2, uint32_t& r3,
                                      uint32_t addr) {
    asm volatile("ldmatrix.sync.aligned.m8n8.x4.shared.b16 {%0,%1,%2,%3}, [%4];"
                 : "=r"(r0), "=r"(r1), "=r"(r2), "=r"(r3) : "r"(addr));
}

// Orderable float <-> uint mapping (total order matching float compare)
__device__ __forceinline__ unsigned int ford(float f) {
    unsigned int u = __float_as_uint(f);
    return (u & 0x80000000u) ? ~u : (u | 0x80000000u);
}
__device__ __forceinline__ float funord(unsigned int r) {
    unsigned int u = (r & 0x80000000u) ? (r & 0x7FFFFFFFu) : ~r;
    return __uint_as_float(u);
}

// key = (orderable(value) << 32) | (VV-1-v): bigger = better, tie -> lower idx
__device__ __forceinline__ u64 mkkey(float val, int v) {
    return ((u64)ford(val) << 32) | (unsigned)(VV - 1 - v);
}
__device__ __forceinline__ int key2idx(u64 k) {
    return VV - 1 - (int)(unsigned)(k & 0xFFFFFFFFu);
}

// Insert x into sorted-descending K-array (drop smallest)
template <int K>
__device__ __forceinline__ void insK(u64 c[K], u64 x) {
    if (x <= c[K - 1]) return;
    c[K - 1] = x;
    #pragma unroll
    for (int i = K - 2; i >= 0; i--) {
        if (c[i + 1] > c[i]) {
            u64 t = c[i]; c[i] = c[i + 1]; c[i + 1] = t;
        }
    }
}

// ---------------------------------------------------------------------------
// Kernel 0: nop (launch-order shim so the GEMM lands in ncu's profiled slot)
// ---------------------------------------------------------------------------
__global__ void nop_kernel() {}

// ---------------------------------------------------------------------------
// Kernel 1: mean-pool partial sums. grid=(NCHUNK, BB), block=256 (float4 each)
// ---------------------------------------------------------------------------
__global__ void __launch_bounds__(256) mean_partial_kernel(const float* __restrict__ patch) {
    int t = threadIdx.x;
    int c = blockIdx.x;
    int b = blockIdx.y;
    const float4* p = reinterpret_cast<const float4*>(
                          patch + ((size_t)b * LL + (size_t)c * LPC) * DD) + t;
    float4 s = make_float4(0.f, 0.f, 0.f, 0.f);
    #pragma unroll 8
    for (int l = 0; l < LPC; l++) {
        float4 v = p[(size_t)l * (DD / 4)];
        s.x += v.x; s.y += v.y; s.z += v.z; s.w += v.w;
    }
    g_part[c][b][t] = s;
}

// ---------------------------------------------------------------------------
// Kernel 2: finalize mean, write exact fp32 + fp16 ts, x norms. grid=BB,block=256
// ---------------------------------------------------------------------------
__global__ void __launch_bounds__(256) finalize_kernel() {
    int b = blockIdx.x;
    int t = threadIdx.x;
    float4 s = make_float4(0.f, 0.f, 0.f, 0.f);
    #pragma unroll
    for (int c = 0; c < NCHUNK; c++) {
        float4 v = g_part[c][b][t];
        s.x += v.x; s.y += v.y; s.z += v.z; s.w += v.w;
    }
    const float inv = 1.0f / (float)LL;
    s.x *= inv; s.y *= inv; s.z *= inv; s.w *= inv;
    reinterpret_cast<float4*>(g_tse[b])[t] = s;
    uint2 h;
    h.x = h2u(__float22half2_rn(make_float2(s.x, s.y)));
    h.y = h2u(__float22half2_rn(make_float2(s.z, s.w)));
    reinterpret_cast<uint2*>(g_ts16[b])[t] = h;

    float ss = s.x * s.x + s.y * s.y + s.z * s.z + s.w * s.w;
    #pragma unroll
    for (int o = 16; o; o >>= 1) ss += __shfl_xor_sync(0xFFFFFFFFu, ss, o);
    __shared__ float red[8];
    if ((t & 31) == 0) red[t >> 5] = ss;
    __syncthreads();
    if (t == 0) {
        float tot = 0.f;
        #pragma unroll
        for (int w = 0; w < 8; w++) tot += red[w];
        g_xnorm[b] = sqrtf(tot);
    }
}

// ---------------------------------------------------------------------------
// Kernel 3: fp16 tensor-core similarity GEMM (m16n8k16, fp32 accum) + fused
// y-norms + fused per-block top-6. Double-buffered smem, ldmatrix fragment
// loads, full-line coalesced B LDGs, 3 CTAs/SM. grid=NBLK, block=256.
// ---------------------------------------------------------------------------
__global__ void __launch_bounds__(256, 3) gemm_kernel(const float* __restrict__ lex,
                                                      float* __restrict__ out_sim) {
    extern __shared__ char smem8[];
    __half* As  = reinterpret_cast<__half*>(smem8);             // [2][64*KPADH]
    __half* Bs  = reinterpret_cast<__half*>(smem8 + OFS_BS);    // [2][128*KPADH]
    float* s_xn = reinterpret_cast<float*>(smem8 + OFS_XN);     // [64]
    float* s_yn = reinterpret_cast<float*>(smem8 + OFS_YN);     // [128]
    float* Cs   = reinterpret_cast<float*>(smem8);              // overlay [64][CSPAD]
    u64*   tmp  = reinterpret_cast<u64*>(smem8 + OFS_TMP);      // overlay [256][BTOP]

    int tid = threadIdx.x;
    int v0 = blockIdx.x * TNB;
    int lane = tid & 31, wid = tid >> 5;
    int g = lane >> 2, t4 = lane & 3;
    int m_base = (wid >> 2) * 32;
    int n_base = (wid & 3) * 32;

    if (tid < BB) s_xn[tid] = g_xnorm[tid];

    // ldmatrix per-lane byte offsets (row stride = 80B; conflict-free phases)
    const uint32_t smem_u32 = (uint32_t)__cvta_generic_to_shared(smem8);
    const uint32_t As_u32 = smem_u32;
    const uint32_t Bs_u32 = smem_u32 + OFS_BS;
    const int a_moff = (((lane >> 3) & 1) << 3) + (lane & 7);   // row within 16
    const int a_khi  = (lane >> 4) << 4;                        // +16B for k-high half
    const uint32_t a_lane_off = (uint32_t)((m_base + a_moff) * 80 + a_khi);
    const int b_noff = ((lane >> 4) << 3) + (lane & 7);         // row within 16 (nt pair)
    const int b_k8   = (((lane >> 3) & 1) << 4);                // +16B for k+8
    const uint32_t b_lane_off = (uint32_t)((n_base + b_noff) * 80 + b_k8);

    // A loader coords (16B of 8 halves per thread)
    const int arow = tid >> 2;
    const int akq  = (tid & 3) * 8;        // halves
    // B loader coords: 8 threads per row, 1 float4 each; 4 row-passes
    const int brow = tid >> 3;             // 0..31 (+32*i)
    const int bkqf = (tid & 7) * 4;        // floats
    const int bkqh = (tid & 7) * 4;        // halves (after fp16 pack)

    float acc[2][4][4];
    #pragma unroll
    for (int mt = 0; mt < 2; mt++)
        #pragma unroll
        for (int nt = 0; nt < 4; nt++)
            #pragma unroll
            for (int r = 0; r < 4; r++) acc[mt][nt][r] = 0.f;
    float yacc[4] = {0.f, 0.f, 0.f, 0.f};

    uint4 a_pre;
    uint2 b_pre[4];    // fp16-packed at load time (register pressure)

    // ---- prologue: load tile 0 into buffer 0 ----
    a_pre = *reinterpret_cast<const uint4*>(&g_ts16[arow][akq]);
    #pragma unroll
    for (int i = 0; i < 4; i++) {
        int v = v0 + brow + 32 * i;
        float4 w = (v < VV)
            ? *reinterpret_cast<const float4*>(&lex[(size_t)v * DD + bkqf])
            : make_float4(0.f, 0.f, 0.f, 0.f);
        yacc[i] += w.x * w.x + w.y * w.y + w.z * w.z + w.w * w.w;
        b_pre[i].x = h2u(__float22half2_rn(make_float2(w.x, w.y)));
        b_pre[i].y = h2u(__float22half2_rn(make_float2(w.z, w.w)));
    }
    {
        *reinterpret_cast<uint4*>(&As[arow * KPADH + akq]) = a_pre;
        #pragma unroll
        for (int i = 0; i < 4; i++)
            *reinterpret_cast<uint2*>(&Bs[(brow + 32 * i) * KPADH + bkqh]) = b_pre[i];
    }
    __syncthreads();

    const int NIT = DD / TKH;  // 32
    for (int it = 0; it < NIT; it++) {
        int cur = it & 1;
        // ---- prefetch next tile (convert + y^2 at load time) ----
        if (it < NIT - 1) {
            int k0 = (it + 1) * TKH;
            a_pre = *reinterpret_cast<const uint4*>(&g_ts16[arow][k0 + akq]);
            #pragma unroll
            for (int i = 0; i < 4; i++) {
                int v = v0 + brow + 32 * i;
                float4 w = (v < VV)
                    ? *reinterpret_cast<const float4*>(&lex[(size_t)v * DD + k0 + bkqf])
                    : make_float4(0.f, 0.f, 0.f, 0.f);
                yacc[i] += w.x * w.x + w.y * w.y + w.z * w.z + w.w * w.w;
                b_pre[i].x = h2u(__float22half2_rn(make_float2(w.x, w.y)));
                b_pre[i].y = h2u(__float22half2_rn(make_float2(w.z, w.w)));
            }
        }
        // ---- compute on current buffer (ldmatrix fragments) ----
        {
            const uint32_t Acur = As_u32 + (uint32_t)(cur * 64 * 80);
            const uint32_t Bcur = Bs_u32 + (uint32_t)(cur * 128 * 80);
            #pragma unroll
            for (int ks = 0; ks < 2; ks++) {
                uint32_t a[2][4], bf[4][2];
                #pragma unroll
                for (int mt = 0; mt < 2; mt++)
                    ldsm4(a[mt][0], a[mt][1], a[mt][2], a[mt][3],
                          Acur + a_lane_off + (uint32_t)(mt * 16 * 80 + ks * 32));
                #pragma unroll
                for (int p = 0; p < 2; p++)
                    ldsm4(bf[2 * p][0], bf[2 * p][1], bf[2 * p + 1][0], bf[2 * p + 1][1],
                          Bcur + b_lane_off + (uint32_t)(p * 16 * 80 + ks * 32));
                #pragma unroll
                for (int mt = 0; mt < 2; mt++)
                    #pragma unroll
                    for (int nt = 0; nt < 4; nt++)
                        mma_f16(acc[mt][nt], a[mt][0], a[mt][1], a[mt][2], a[mt][3],
                                bf[nt][0], bf[nt][1]);
            }
        }
        // ---- store prefetched tile into other buffer ----
        if (it < NIT - 1) {
            __half* Ab = As + (1 - cur) * 64 * KPADH;
            __half* Bb = Bs + (1 - cur) * 128 * KPADH;
            *reinterpret_cast<uint4*>(&Ab[arow * KPADH + akq]) = a_pre;
            #pragma unroll
            for (int i = 0; i < 4; i++)
                *reinterpret_cast<uint2*>(&Bb[(brow + 32 * i) * KPADH + bkqh]) = b_pre[i];
            __syncthreads();
        }
    }

    // ---- y norms: reduce over the 8 threads sharing each row ----
    #pragma unroll
    for (int i = 0; i < 4; i++) {
        float ys = yacc[i];
        ys += __shfl_down_sync(0xFFFFFFFFu, ys, 4, 8);
        ys += __shfl_down_sync(0xFFFFFFFFu, ys, 2, 8);
        ys += __shfl_down_sync(0xFFFFFFFFu, ys, 1, 8);
        if ((tid & 7) == 0) {
            int n = brow + 32 * i;
            float yn = sqrtf(ys);
            s_yn[n] = yn;
            if (v0 + n < VV) g_ynorm[v0 + n] = yn;
        }
    }
    __syncthreads();  // all warps done with As/Bs; s_yn ready; overlay begins

    // ---- stage normalized tile in smem (Cs overlays As/Bs) ----
    #pragma unroll
    for (int mt = 0; mt < 2; mt++) {
        int m0 = m_base + 16 * mt + g;
        float xn0 = s_xn[m0], xn1 = s_xn[m0 + 8];
        #pragma unroll
        for (int nt = 0; nt < 4; nt++) {
            int ncol = n_base + 8 * nt + 2 * t4;
            #pragma unroll
            for (int j = 0; j < 2; j++) {
                int v = v0 + ncol + j;
                float yn = s_yn[ncol + j];
                float s0 = acc[mt][nt][j]     / fmaxf(xn0 * yn, 1e-8f);
                float s1 = acc[mt][nt][2 + j] / fmaxf(xn1 * yn, 1e-8f);
                if (v >= VV) { s0 = -3.4e38f; s1 = -3.4e38f; }
                Cs[m0 * CSPAD + ncol + j]       = s0;
                Cs[(m0 + 8) * CSPAD + ncol + j] = s1;
            }
        }
    }
    __syncthreads();

    // ---- coalesced out_sim write ----
    #pragma unroll
    for (int i = 0; i < 32; i++) {
        int idx = tid + i * 256;
        int m = idx >> 7, col = idx & 127;
        int v = v0 + col;
        if (v < VV)
            out_sim[(size_t)m * VV + v] = Cs[m * CSPAD + col];
    }

    // ---- per-row top-6: 4 threads/row, 32 cols each ----
    {
        int row = tid >> 2, q = tid & 3;
        u64 t6[BTOP] = {0, 0, 0, 0, 0, 0};
        #pragma unroll
        for (int i = 0; i < 32; i++) {
            int col = q * 32 + i;
            int v = v0 + col;
            if (v < VV) insK<BTOP>(t6, mkkey(Cs[row * CSPAD + col], v));
        }
        #pragma unroll
        for (int i = 0; i < BTOP; i++) tmp[tid * BTOP + i] = t6[i];
    }
    __syncthreads();
    if (tid < BB) {
        u64 t6[BTOP] = {0, 0, 0, 0, 0, 0};
        #pragma unroll
        for (int q = 0; q < 4; q++)
            #pragma unroll
            for (int i = 0; i < BTOP; i++)
                insK<BTOP>(t6, tmp[(tid * 4 + q) * BTOP + i]);
        #pragma unroll
        for (int i = 0; i < BTOP; i++) g_btop[tid][blockIdx.x][i] = t6[i];
    }
}

// ---------------------------------------------------------------------------
// Kernel 4: merge per-block top-6 keys -> approx top-5 -> threshold candidates
// -> exact fp32 recompute -> exact select -> gather. grid=BB, block=512.
// ---------------------------------------------------------------------------
__global__ void __launch_bounds__(512) merge_kernel(const float* __restrict__ lex,
                                                    float* __restrict__ out_topk) {
    int b = blockIdx.x;
    int t = threadIdx.x;
    int lane = t & 31, wid = t >> 5;

    __shared__ u64   wtop[16][5];
    __shared__ float s_thresh;
    __shared__ int   cand[NCAND];
    __shared__ float cval[NCAND];
    __shared__ int   ncand;
    __shared__ int   selci[TOPK];
    __shared__ int   selfin[TOPK];

    const u64* keys = &g_btop[b][0][0];
    const int NK = NBLK * BTOP;  // 2358

    u64 t5[5] = {0, 0, 0, 0, 0};
    for (int i = t; i < NK; i += 512) insK<5>(t5, keys[i]);
    #pragma unroll
    for (int o = 16; o; o >>= 1) {
        u64 ot[5];
        #pragma unroll
        for (int i = 0; i < 5; i++) ot[i] = __shfl_xor_sync(0xFFFFFFFFu, t5[i], o);
        #pragma unroll
        for (int i = 0; i < 5; i++) insK<5>(t5, ot[i]);
    }
    if (lane == 0) {
        #pragma unroll
        for (int i = 0; i < 5; i++) wtop[wid][i] = t5[i];
    }
    __syncthreads();
    if (wid == 0) {
        const u64* flat = &wtop[0][0];  // 80 keys
        u64 m5[5] = {0, 0, 0, 0, 0};
        insK<5>(m5, flat[lane]);
        insK<5>(m5, flat[lane + 32]);
        if (lane < 16) insK<5>(m5, flat[lane + 64]);
        #pragma unroll
        for (int o = 16; o; o >>= 1) {
            u64 ot[5];
            #pragma unroll
            for (int i = 0; i < 5; i++) ot[i] = __shfl_xor_sync(0xFFFFFFFFu, m5[i], o);
            #pragma unroll
            for (int i = 0; i < 5; i++) insK<5>(m5, ot[i]);
        }
        if (lane == 0) {
            s_thresh = funord((unsigned)(m5[4] >> 32)) - 5e-4f;
            ncand = 0;
        }
    }
    __syncthreads();

    float thr = s_thresh;
    for (int i = t; i < NK; i += 512) {
        u64 k = keys[i];
        if (funord((unsigned)(k >> 32)) >= thr) {
            int slot = atomicAdd(&ncand, 1);
            if (slot < NCAND) cand[slot] = key2idx(k);
        }
    }
    __syncthreads();
    int nc = min(ncand, NCAND);

    {
        const float4* ts4 = reinterpret_cast<const float4*>(g_tse[b]);
        for (int ci = wid; ci < nc; ci += 16) {
            int v = cand[ci];
            const float4* lx4 = reinterpret_cast<const float4*>(lex + (size_t)v * DD);
            float d = 0.f;
            #pragma unroll
            for (int j = 0; j < 8; j++) {
                float4 a = ts4[j * 32 + lane];
                float4 c = lx4[j * 32 + lane];
                d += a.x * c.x + a.y * c.y + a.z * c.z + a.w * c.w;
            }
            #pragma unroll
            for (int o = 16; o; o >>= 1) d += __shfl_xor_sync(0xFFFFFFFFu, d, o);
            if (lane == 0)
                cval[ci] = d / fmaxf(g_xnorm[b] * g_ynorm[v], 1e-8f);
        }
    }
    __syncthreads();

    if (t < 32) {
        for (int j = 0; j < TOPK; j++) {
            float bv = -1e30f;
            int bvi = 0x7FFFFFFF;
            int bci = -1;
            for (int ci = t; ci < nc; ci += 32) {
                bool used = false;
                #pragma unroll
                for (int jj = 0; jj < TOPK; jj++)
                    if (jj < j && selci[jj] == ci) used = true;
                if (used) continue;
                float x = cval[ci];
                int v = cand[ci];
                if (x > bv || (x == bv && v < bvi)) { bv = x; bvi = v; bci = ci; }
            }
            #pragma unroll
            for (int o = 16; o; o >>= 1) {
                float ov  = __shfl_xor_sync(0xFFFFFFFFu, bv, o);
                int   ovi = __shfl_xor_sync(0xFFFFFFFFu, bvi, o);
                int   oci = __shfl_xor_sync(0xFFFFFFFFu, bci, o);
                if (ov > bv || (ov == bv && ovi < bvi)) { bv = ov; bvi = ovi; bci = oci; }
            }
            if (t == 0) { selci[j] = bci; selfin[j] = bvi; }
            __syncwarp();
        }
    }
    __syncthreads();

    for (int j = 0; j < TOPK; j++) {
        const float4* src = reinterpret_cast<const float4*>(lex + (size_t)selfin[j] * DD);
        float4* dst = reinterpret_cast<float4*>(out_topk + ((size_t)b * TOPK + j) * DD);
        if (t < DD / 4) dst[t] = src[t];
    }
}

// ---------------------------------------------------------------------------
extern "C" void kernel_launch(void* const* d_in, const int* in_sizes, int n_in,
                              void* d_out, int out_size) {
    const float* patch = (const float*)d_in[0];
    const float* lex   = (const float*)d_in[1];
    float* out      = (float*)d_out;
    float* out_topk = out;                                  // [64][5][1024]
    float* out_sim  = out + (size_t)BB * TOPK * DD;         // [64][50257]

    cudaFuncSetAttribute(gemm_kernel, cudaFuncAttributeMaxDynamicSharedMemorySize,
                         GEMM_SMEM);

    mean_partial_kernel<<<dim3(NCHUNK, BB), 256>>>(patch);
    finalize_kernel<<<BB, 256>>>();
    nop_kernel<<<1, 32>>>();   // shim: makes gemm the 4th launch (profiled slot)
    gemm_kernel<<<NBLK, 256, GEMM_SMEM>>>(lex, out_sim);
    merge_kernel<<<BB, 512>>>(lex, out_topk);
}